// round 16
// baseline (speedup 1.0000x reference)
#include <cuda_runtime.h>
#include <cuda_bf16.h>
#include <cstdint>
#include <math.h>

// Problem constants
#define M_TOT 4096      // 2*N*T
#define DIM   512
#define TSPAN 16
#define NEG_INV (1.0f/31.0f)

// Device scratch (no allocs allowed)
__device__ __nv_bfloat16 g_znb[M_TOT * DIM];   // normalized z, bf16 (4 MB)
__device__ float g_rowExp[M_TOT];              // zero-init; reset by finalize
__device__ float g_rowNum[M_TOT];
__device__ int   g_blockCnt[32];               // groups-done per 128-row block

// ---------------------------------------------------------------------------
// helpers
// ---------------------------------------------------------------------------
__device__ __forceinline__ uint32_t smem_u32(const void* p) {
    return (uint32_t)__cvta_generic_to_shared(p);
}
__device__ __forceinline__ void ldsm4(uint32_t addr, uint32_t* r) {
    asm volatile("ldmatrix.sync.aligned.m8n8.x4.shared.b16 {%0,%1,%2,%3}, [%4];"
                 : "=r"(r[0]), "=r"(r[1]), "=r"(r[2]), "=r"(r[3]) : "r"(addr));
}
__device__ __forceinline__ void mma16816(float* c, const uint32_t* a, uint32_t b0, uint32_t b1) {
    asm volatile("mma.sync.aligned.m16n8k16.row.col.f32.bf16.bf16.f32 "
                 "{%0,%1,%2,%3}, {%4,%5,%6,%7}, {%8,%9}, {%0,%1,%2,%3};"
                 : "+f"(c[0]), "+f"(c[1]), "+f"(c[2]), "+f"(c[3])
                 : "r"(a[0]), "r"(a[1]), "r"(a[2]), "r"(a[3]), "r"(b0), "r"(b1));
}
#define CP_ASYNC16(dst, src) \
    asm volatile("cp.async.cg.shared.global [%0], [%1], 16;\n" :: "r"(dst), "l"(src))
#define CP_COMMIT() asm volatile("cp.async.commit_group;\n" ::: "memory")
#define CP_WAIT2()  asm volatile("cp.async.wait_group 2;\n" ::: "memory")

// FFMA-only exp(10*a): 2^(a*14.4269504), degree-5 poly on [-0.5, 0.5]
__device__ __forceinline__ float exp10x(float a) {
    const float L = 14.4269504f;
    const float tk = __fmaf_rn(a, L, 12582912.0f);
    const int   X  = __float_as_int(tk);
    const float kf = tk - 12582912.0f;
    const float f  = __fmaf_rn(a, L, -kf);
    float p = 1.3333558e-3f;
    p = __fmaf_rn(p, f, 9.6181291e-3f);
    p = __fmaf_rn(p, f, 5.5504109e-2f);
    p = __fmaf_rn(p, f, 2.4022651e-1f);
    p = __fmaf_rn(p, f, 6.9314718e-1f);
    p = __fmaf_rn(p, f, 1.0f);
    return p * __int_as_float((X << 23) + 0x3F800000);
}

// ---------------------------------------------------------------------------
// Fused kernel: CTAs 0..127 first run prep for trajectory group = blockIdx,
// publish readiness of the two 128-row blocks they feed, then all 528 CTAs
// wait for their (bi, bj) blocks and run the symmetric GEMM + exp-sum.
// ---------------------------------------------------------------------------
#define BT 128
#define KC 64
#define NCHUNK (DIM / KC)                  // 8
#define STAGE_BYTES 32768                  // A 16KB + B 16KB per stage
#define SMEM_BYTES  (3 * STAGE_BYTES)      // 98304 (prep scratch fits inside)

__global__ void __launch_bounds__(512, 2) gemm_kernel(const float* __restrict__ z) {
    extern __shared__ __align__(16) unsigned char smem[];
    __shared__ float sRow[BT], sCol[BT];

    const int tid = threadIdx.x, lane = tid & 31, wid = tid >> 5;

    // ================= Prep phase (CTAs 0..127, one trajectory group) =======
    if (blockIdx.x < 128) {
        const int grp = blockIdx.x;
        float* sZ = (float*)smem;            // [32][DIM]  64 KB
        float* SP = sZ + 32 * DIM;           // [2][DIM]    4 KB

        // Warp w handles local rows w (view 0) and w+16 (view 1)
        #pragma unroll
        for (int half = 0; half < 2; ++half) {
            const int row = grp * TSPAN + wid + half * (M_TOT / 2);
            const int lrow = wid + half * 16;
            const float4* src = (const float4*)(z + (size_t)row * DIM);
            float4 v[4]; float ss = 0.f;
            #pragma unroll
            for (int k = 0; k < 4; ++k) {
                v[k] = src[lane + k * 32];
                ss += v[k].x*v[k].x + v[k].y*v[k].y + v[k].z*v[k].z + v[k].w*v[k].w;
            }
            #pragma unroll
            for (int o = 16; o; o >>= 1) ss += __shfl_xor_sync(0xffffffffu, ss, o);
            const float rn = 1.0f / fmaxf(sqrtf(ss), 1e-8f);
            __nv_bfloat162* dst = (__nv_bfloat162*)(g_znb + (size_t)row * DIM);
            float4* srow = (float4*)(sZ + lrow * DIM);
            #pragma unroll
            for (int k = 0; k < 4; ++k) {
                const int idx = lane + k * 32;
                float4 x;
                x.x = v[k].x*rn; x.y = v[k].y*rn; x.z = v[k].z*rn; x.w = v[k].w*rn;
                srow[idx] = x;
                dst[idx*2 + 0] = __floats2bfloat162_rn(x.x, x.y);
                dst[idx*2 + 1] = __floats2bfloat162_rn(x.z, x.w);
            }
        }
        __syncthreads();

        // Group partial sums per view half
        {
            const int d = tid;               // 0..511
            float s0 = 0.f, s1 = 0.f;
            #pragma unroll
            for (int r = 0; r < 16; ++r) {
                s0 += sZ[r * DIM + d];
                s1 += sZ[(16 + r) * DIM + d];
            }
            SP[d] = s0; SP[DIM + d] = s1;
        }
        __syncthreads();

        // Numerator for the warp's two rows
        #pragma unroll
        for (int half = 0; half < 2; ++half) {
            const int row = grp * TSPAN + wid + half * (M_TOT / 2);
            const int lrow = wid + half * 16;
            float d1 = 0.f, d2 = 0.f;
            const float4* zr = (const float4*)(sZ + lrow * DIM);
            const float4* s0 = (const float4*)SP;
            const float4* s1 = (const float4*)(SP + DIM);
            #pragma unroll
            for (int j = 0; j < 4; ++j) {
                const float4 a  = zr[lane + j * 32];
                const float4 p0 = s0[lane + j * 32];
                const float4 p1 = s1[lane + j * 32];
                d1 += a.x*(p0.x+p1.x) + a.y*(p0.y+p1.y) + a.z*(p0.z+p1.z) + a.w*(p0.w+p1.w);
                d2 += a.x*a.x + a.y*a.y + a.z*a.z + a.w*a.w;
            }
            #pragma unroll
            for (int o = 16; o; o >>= 1) {
                d1 += __shfl_xor_sync(0xffffffffu, d1, o);
                d2 += __shfl_xor_sync(0xffffffffu, d2, o);
            }
            if (lane == 0) g_rowNum[row] = 10.0f * (d1 - d2);
        }

        __threadfence();          // publish g_znb / g_rowNum before flagging
        __syncthreads();
        if (tid == 0) {
            atomicAdd(&g_blockCnt[grp >> 3], 1);            // view-0 block
            atomicAdd(&g_blockCnt[16 + (grp >> 3)], 1);     // view-1 block
        }
    }

    // ================= GEMM phase (all 528 CTAs) ============================
    // Decode upper-triangular tile index: f(b) = b*(65-b)/2
    int idx = blockIdx.x;
    int bi = (int)(32.5f - sqrtf(1056.25f - 2.0f * (float)idx));
    if (bi < 0) bi = 0; if (bi > 31) bi = 31;
    while (bi * (65 - bi) / 2 > idx) --bi;
    while ((bi + 1) * (64 - bi) / 2 <= idx) ++bi;
    const int bj = bi + (idx - bi * (65 - bi) / 2);
    const bool diag = (bi == bj);
    const int rowBase = bi * BT, colBase = bj * BT;

    // Wait for both source blocks to be fully prepped
    if (tid == 0) {
        while (atomicAdd(&g_blockCnt[bi], 0) < 8) { }
        while (atomicAdd(&g_blockCnt[bj], 0) < 8) { }
    }
    __syncthreads();

    const int warp_m = wid & 3;        // 4 x 32 rows
    const int warp_n = wid >> 2;       // 4 x 32 cols
    const uint32_t sbase = smem_u32(smem);

    if (tid < BT) { sRow[tid] = 0.f; sCol[tid] = 0.f; }

    // Loader: 4 threads per row, 2 x 16B units each; swizzled 128B rows
    const int lr = tid >> 2;                    // 0..127
    const int lu = (tid & 3) * 2;               // 0,2,4,6
    const __nv_bfloat16* gA = g_znb + (size_t)(rowBase + lr) * DIM + lu * 8;
    const __nv_bfloat16* gB = g_znb + (size_t)(colBase + lr) * DIM + lu * 8;
    uint32_t dstU[2];
    #pragma unroll
    for (int u = 0; u < 2; ++u)
        dstU[u] = sbase + lr * 128 + (((lu + u) ^ (lr & 7)) << 4);

    // Per-warp ldsm lane-row bases
    const int mrowA = warp_m * 32 + (lane & 15);                       // + mt*16
    const int uA_half = lane >> 4;                                     // ks*2 + this
    const int nrowB = warp_n * 32 + ((lane >> 4) << 3) + (lane & 7);   // + np*16
    const int uB_half = (lane >> 3) & 1;

    float acc[2][4][4];
    #pragma unroll
    for (int a = 0; a < 2; ++a)
        #pragma unroll
        for (int b = 0; b < 4; ++b)
            #pragma unroll
            for (int i = 0; i < 4; ++i) acc[a][b][i] = 0.f;

    // Prologue: stage chunks 0, 1
    #pragma unroll
    for (int s = 0; s < 2; ++s) {
        const uint32_t so = s * STAGE_BYTES;
        #pragma unroll
        for (int u = 0; u < 2; ++u) CP_ASYNC16(dstU[u] + so,         gA + s * KC + u * 8);
        #pragma unroll
        for (int u = 0; u < 2; ++u) CP_ASYNC16(dstU[u] + so + 16384, gB + s * KC + u * 8);
        CP_COMMIT();
    }

    // Main loop: prefetch first, commit every iter, wait_group 2.
    for (int ch = 0; ch < NCHUNK; ++ch) {
        if (ch + 2 < NCHUNK) {
            const uint32_t so = ((ch + 2) % 3) * STAGE_BYTES;
            #pragma unroll
            for (int u = 0; u < 2; ++u) CP_ASYNC16(dstU[u] + so,         gA + (ch + 2) * KC + u * 8);
            #pragma unroll
            for (int u = 0; u < 2; ++u) CP_ASYNC16(dstU[u] + so + 16384, gB + (ch + 2) * KC + u * 8);
        }
        CP_COMMIT();            // every iter -> uniform wait bound
        CP_WAIT2();             // chunk ch resident
        __syncthreads();

        const uint32_t Ab = sbase + (ch % 3) * STAGE_BYTES;
        const uint32_t Bb = Ab + 16384;
        #pragma unroll
        for (int ks = 0; ks < 4; ++ks) {
            uint32_t afr[2][4], bfr[2][4];
            const int u = ks * 2 + uA_half;
            #pragma unroll
            for (int mt = 0; mt < 2; ++mt) {
                const int m = mrowA + mt * 16;
                ldsm4(Ab + m * 128 + ((u ^ (m & 7)) << 4), afr[mt]);
            }
            const int ub = ks * 2 + uB_half;
            #pragma unroll
            for (int np = 0; np < 2; ++np) {
                const int n = nrowB + np * 16;
                ldsm4(Bb + n * 128 + ((ub ^ (n & 7)) << 4), bfr[np]);
            }
            #pragma unroll
            for (int mt = 0; mt < 2; ++mt)
                #pragma unroll
                for (int np = 0; np < 2; ++np) {
                    mma16816(acc[mt][np * 2 + 0], afr[mt], bfr[np][0], bfr[np][1]);
                    mma16816(acc[mt][np * 2 + 1], afr[mt], bfr[np][2], bfr[np][3]);
                }
        }
        __syncthreads();        // protect stage about to be overwritten
    }

    // ---- Epilogue: exp + row sums (and col sums for off-diagonal tiles) ----
    const int gq = lane >> 2, tq = lane & 3;
    float accRow[2][2], accCol[4][2];
    #pragma unroll
    for (int a = 0; a < 2; ++a) { accRow[a][0] = accRow[a][1] = 0.f; }
    #pragma unroll
    for (int a = 0; a < 4; ++a) { accCol[a][0] = accCol[a][1] = 0.f; }

    #pragma unroll
    for (int mt = 0; mt < 2; ++mt)
        #pragma unroll
        for (int nn = 0; nn < 4; ++nn)
            #pragma unroll
            for (int i = 0; i < 4; ++i) {
                float e = exp10x(acc[mt][nn][i]);
                if (diag) {
                    const int dR = warp_m * 32 + mt * 16 + gq + (i >> 1) * 8;
                    const int dC = warp_n * 32 + nn * 8 + tq * 2 + (i & 1);
                    if (dR == dC) e = 0.f;
                }
                accRow[mt][i >> 1] += e;
                accCol[nn][i & 1]  += e;
            }

    #pragma unroll
    for (int o = 1; o <= 2; o <<= 1)
        #pragma unroll
        for (int mt = 0; mt < 2; ++mt) {
            accRow[mt][0] += __shfl_xor_sync(0xffffffffu, accRow[mt][0], o);
            accRow[mt][1] += __shfl_xor_sync(0xffffffffu, accRow[mt][1], o);
        }
    if (!diag) {
        #pragma unroll
        for (int o = 4; o <= 16; o <<= 1)
            #pragma unroll
            for (int nn = 0; nn < 4; ++nn) {
                accCol[nn][0] += __shfl_xor_sync(0xffffffffu, accCol[nn][0], o);
                accCol[nn][1] += __shfl_xor_sync(0xffffffffu, accCol[nn][1], o);
            }
    }

    // sRow/sCol were zeroed before the mainloop; its syncs ordered that.
    if (tq == 0) {
        #pragma unroll
        for (int mt = 0; mt < 2; ++mt)
            #pragma unroll
            for (int ih = 0; ih < 2; ++ih)
                atomicAdd(&sRow[warp_m * 32 + mt * 16 + gq + ih * 8], accRow[mt][ih]);
    }
    if (!diag && gq == 0) {
        #pragma unroll
        for (int nn = 0; nn < 4; ++nn)
            #pragma unroll
            for (int j = 0; j < 2; ++j)
                atomicAdd(&sCol[warp_n * 32 + nn * 8 + tq * 2 + j], accCol[nn][j]);
    }
    __syncthreads();
    if (tid < BT) {
        atomicAdd(&g_rowExp[rowBase + tid], sRow[tid]);
        if (!diag) atomicAdd(&g_rowExp[colBase + tid], sCol[tid]);
    }
}

// ---------------------------------------------------------------------------
// Finalize: per-row loss + global mean; resets persistent state for the next
// (graph-replayed) invocation.
// ---------------------------------------------------------------------------
__global__ void finalize_kernel(float* __restrict__ out) {
    int tid = threadIdx.x;   // 1024 threads
    float s = 0.f;
    #pragma unroll
    for (int k = 0; k < 4; ++k) {
        int r = tid + k * 1024;
        s += g_rowNum[r] * NEG_INV - __logf(g_rowExp[r]);
        g_rowExp[r] = 0.f;               // reset for next invocation
    }
    if (tid < 32) g_blockCnt[tid] = 0;   // reset readiness flags
    #pragma unroll
    for (int o = 16; o; o >>= 1) s += __shfl_xor_sync(0xffffffffu, s, o);
    __shared__ float ws[32];
    if ((tid & 31) == 0) ws[tid >> 5] = s;
    __syncthreads();
    if (tid < 32) {
        float v = ws[tid];
        #pragma unroll
        for (int o = 16; o; o >>= 1) v += __shfl_xor_sync(0xffffffffu, v, o);
        if (tid == 0) out[0] = -v / (float)M_TOT;
    }
}

// ---------------------------------------------------------------------------
extern "C" void kernel_launch(void* const* d_in, const int* in_sizes, int n_in,
                              void* d_out, int out_size) {
    const float* z = (const float*)d_in[0];
    if (n_in > 1 && in_sizes[0] != M_TOT * DIM) z = (const float*)d_in[1];

    cudaFuncSetAttribute(gemm_kernel, cudaFuncAttributeMaxDynamicSharedMemorySize, SMEM_BYTES);

    gemm_kernel<<<528, 512, SMEM_BYTES>>>(z);
    finalize_kernel<<<1, 1024>>>((float*)d_out);
}

// round 17
// speedup vs baseline: 1.0943x; 1.0943x over previous
#include <cuda_runtime.h>
#include <cuda_bf16.h>
#include <cstdint>
#include <math.h>

// Problem constants
#define M_TOT 4096      // 2*N*T
#define DIM   512
#define TSPAN 16
#define NEG_INV (1.0f/31.0f)

// Device scratch (no allocs allowed)
__device__ __nv_bfloat16 g_znb[M_TOT * DIM];   // normalized z, bf16 (4 MB)
__device__ float g_rowExp[M_TOT];
__device__ float g_rowNum[M_TOT];

// ---------------------------------------------------------------------------
// helpers
// ---------------------------------------------------------------------------
__device__ __forceinline__ uint32_t smem_u32(const void* p) {
    return (uint32_t)__cvta_generic_to_shared(p);
}
__device__ __forceinline__ void ldsm4(uint32_t addr, uint32_t* r) {
    asm volatile("ldmatrix.sync.aligned.m8n8.x4.shared.b16 {%0,%1,%2,%3}, [%4];"
                 : "=r"(r[0]), "=r"(r[1]), "=r"(r[2]), "=r"(r[3]) : "r"(addr));
}
__device__ __forceinline__ void mma16816(float* c, const uint32_t* a, uint32_t b0, uint32_t b1) {
    asm volatile("mma.sync.aligned.m16n8k16.row.col.f32.bf16.bf16.f32 "
                 "{%0,%1,%2,%3}, {%4,%5,%6,%7}, {%8,%9}, {%0,%1,%2,%3};"
                 : "+f"(c[0]), "+f"(c[1]), "+f"(c[2]), "+f"(c[3])
                 : "r"(a[0]), "r"(a[1]), "r"(a[2]), "r"(a[3]), "r"(b0), "r"(b1));
}
#define CP_ASYNC16(dst, src) \
    asm volatile("cp.async.cg.shared.global [%0], [%1], 16;\n" :: "r"(dst), "l"(src))
#define CP_COMMIT() asm volatile("cp.async.commit_group;\n" ::: "memory")
#define CP_WAIT1()  asm volatile("cp.async.wait_group 1;\n" ::: "memory")

// FFMA-only exp(10*a): 2^(a*14.4269504), degree-5 poly on [-0.5, 0.5]
__device__ __forceinline__ float exp10x(float a) {
    const float L = 14.4269504f;
    const float tk = __fmaf_rn(a, L, 12582912.0f);
    const int   X  = __float_as_int(tk);
    const float kf = tk - 12582912.0f;
    const float f  = __fmaf_rn(a, L, -kf);
    float p = 1.3333558e-3f;
    p = __fmaf_rn(p, f, 9.6181291e-3f);
    p = __fmaf_rn(p, f, 5.5504109e-2f);
    p = __fmaf_rn(p, f, 2.4022651e-1f);
    p = __fmaf_rn(p, f, 6.9314718e-1f);
    p = __fmaf_rn(p, f, 1.0f);
    return p * __int_as_float((X << 23) + 0x3F800000);
}

// ---------------------------------------------------------------------------
// Kernel 1 (fused prep + groupnum), 1024 threads: warp w <-> group row w.
// (R13/R15-proven, unchanged)
// ---------------------------------------------------------------------------
#define PREP_SMEM ((32 * DIM + 2 * DIM) * 4)   // 64KB + 4KB

__global__ void __launch_bounds__(1024) prep_kernel(const float* __restrict__ z) {
    extern __shared__ float sm[];
    float* sZ = sm;                  // [32][DIM]
    float* SP = sm + 32 * DIM;       // [2][DIM] partial group sums
    const int grp = blockIdx.x, tid = threadIdx.x;
    const int wid = tid >> 5, lane = tid & 31;

    const int row = grp * TSPAN + (wid & 15) + (wid >> 4) * (M_TOT / 2);
    {
        const float4* src = (const float4*)(z + (size_t)row * DIM);
        float4 v[4]; float ss = 0.f;
        #pragma unroll
        for (int k = 0; k < 4; ++k) {
            v[k] = src[lane + k * 32];
            ss += v[k].x*v[k].x + v[k].y*v[k].y + v[k].z*v[k].z + v[k].w*v[k].w;
        }
        #pragma unroll
        for (int o = 16; o; o >>= 1) ss += __shfl_xor_sync(0xffffffffu, ss, o);
        const float rn = 1.0f / fmaxf(sqrtf(ss), 1e-8f);
        __nv_bfloat162* dst = (__nv_bfloat162*)(g_znb + (size_t)row * DIM);
        float4* srow = (float4*)(sZ + wid * DIM);
        #pragma unroll
        for (int k = 0; k < 4; ++k) {
            const int idx = lane + k * 32;
            float4 x;
            x.x = v[k].x*rn; x.y = v[k].y*rn; x.z = v[k].z*rn; x.w = v[k].w*rn;
            srow[idx] = x;
            dst[idx*2 + 0] = __floats2bfloat162_rn(x.x, x.y);
            dst[idx*2 + 1] = __floats2bfloat162_rn(x.z, x.w);
        }
    }
    if (lane == 0) g_rowExp[row] = 0.f;
    __syncthreads();

    {
        const int d = tid & (DIM - 1);
        const int half = tid >> 9;           // 0 or 1
        float s = 0.f;
        #pragma unroll
        for (int r = 0; r < 16; ++r) s += sZ[(half * 16 + r) * DIM + d];
        SP[half * DIM + d] = s;
    }
    __syncthreads();

    {
        float d1 = 0.f, d2 = 0.f;
        const float4* zr  = (const float4*)(sZ + wid * DIM);
        const float4* s0  = (const float4*)SP;
        const float4* s1  = (const float4*)(SP + DIM);
        #pragma unroll
        for (int j = 0; j < 4; ++j) {
            const float4 a  = zr[lane + j * 32];
            const float4 p0 = s0[lane + j * 32];
            const float4 p1 = s1[lane + j * 32];
            d1 += a.x*(p0.x+p1.x) + a.y*(p0.y+p1.y) + a.z*(p0.z+p1.z) + a.w*(p0.w+p1.w);
            d2 += a.x*a.x + a.y*a.y + a.z*a.z + a.w*a.w;
        }
        #pragma unroll
        for (int o = 16; o; o >>= 1) {
            d1 += __shfl_xor_sync(0xffffffffu, d1, o);
            d2 += __shfl_xor_sync(0xffffffffu, d2, o);
        }
        if (lane == 0) g_rowNum[row] = 10.0f * (d1 - d2);
    }
}

// ---------------------------------------------------------------------------
// Kernel 2: bf16 symmetric fused GEMM + exp-sum.
// 528 upper-triangular 128x128 tiles, 512 threads (16 warps, 32x32 warp
// tiles). 3-stage cp.async pipeline, ONE barrier per K-chunk:
//   wait1 -> sync -> prefetch(ch+2) -> commit -> compute(ch)
// ---------------------------------------------------------------------------
#define BT 128
#define KC 64
#define NCHUNK (DIM / KC)                  // 8
#define STAGE_BYTES 32768                  // A 16KB + B 16KB per stage
#define SMEM_BYTES  (3 * STAGE_BYTES)      // 98304

__global__ void __launch_bounds__(512, 2) gemm_kernel() {
    extern __shared__ __align__(16) unsigned char smem[];
    __shared__ float sRow[BT], sCol[BT];

    // Decode upper-triangular tile index: f(b) = b*(65-b)/2
    int idx = blockIdx.x;
    int bi = (int)(32.5f - sqrtf(1056.25f - 2.0f * (float)idx));
    if (bi < 0) bi = 0; if (bi > 31) bi = 31;
    while (bi * (65 - bi) / 2 > idx) --bi;
    while ((bi + 1) * (64 - bi) / 2 <= idx) ++bi;
    const int bj = bi + (idx - bi * (65 - bi) / 2);
    const bool diag = (bi == bj);
    const int rowBase = bi * BT, colBase = bj * BT;

    const int tid = threadIdx.x, lane = tid & 31, wid = tid >> 5;
    const int warp_m = wid & 3;        // 4 x 32 rows
    const int warp_n = wid >> 2;       // 4 x 32 cols
    const uint32_t sbase = smem_u32(smem);

    if (tid < BT) { sRow[tid] = 0.f; sCol[tid] = 0.f; }

    // Loader: 4 threads per row, 2 x 16B units each; swizzled 128B rows
    const int lr = tid >> 2;                    // 0..127
    const int lu = (tid & 3) * 2;               // 0,2,4,6
    const __nv_bfloat16* gA = g_znb + (size_t)(rowBase + lr) * DIM + lu * 8;
    const __nv_bfloat16* gB = g_znb + (size_t)(colBase + lr) * DIM + lu * 8;
    uint32_t dstU[2];
    #pragma unroll
    for (int u = 0; u < 2; ++u)
        dstU[u] = sbase + lr * 128 + (((lu + u) ^ (lr & 7)) << 4);

    // Per-warp ldsm lane-row bases
    const int mrowA = warp_m * 32 + (lane & 15);                       // + mt*16
    const int uA_half = lane >> 4;                                     // ks*2 + this
    const int nrowB = warp_n * 32 + ((lane >> 4) << 3) + (lane & 7);   // + np*16
    const int uB_half = (lane >> 3) & 1;

    float acc[2][4][4];
    #pragma unroll
    for (int a = 0; a < 2; ++a)
        #pragma unroll
        for (int b = 0; b < 4; ++b)
            #pragma unroll
            for (int i = 0; i < 4; ++i) acc[a][b][i] = 0.f;

    // Prologue: stage chunks 0, 1 (one commit group each)
    #pragma unroll
    for (int s = 0; s < 2; ++s) {
        const uint32_t so = s * STAGE_BYTES;
        #pragma unroll
        for (int u = 0; u < 2; ++u) CP_ASYNC16(dstU[u] + so,         gA + s * KC + u * 8);
        #pragma unroll
        for (int u = 0; u < 2; ++u) CP_ASYNC16(dstU[u] + so + 16384, gB + s * KC + u * 8);
        CP_COMMIT();
    }

    // Main loop: ONE barrier per chunk.
    // At iter ch: commits so far end with chunk ch+1 -> wait1 makes chunk ch
    // resident. The barrier also protects stage (ch+2)%3 == (ch-1)%3, whose
    // consumption (iter ch-1 compute) happened before this barrier.
    for (int ch = 0; ch < NCHUNK; ++ch) {
        CP_WAIT1();
        __syncthreads();
        if (ch + 2 < NCHUNK) {
            const uint32_t so = ((ch + 2) % 3) * STAGE_BYTES;
            #pragma unroll
            for (int u = 0; u < 2; ++u) CP_ASYNC16(dstU[u] + so,         gA + (ch + 2) * KC + u * 8);
            #pragma unroll
            for (int u = 0; u < 2; ++u) CP_ASYNC16(dstU[u] + so + 16384, gB + (ch + 2) * KC + u * 8);
        }
        CP_COMMIT();            // every iter -> uniform wait bound

        const uint32_t Ab = sbase + (ch % 3) * STAGE_BYTES;
        const uint32_t Bb = Ab + 16384;
        #pragma unroll
        for (int ks = 0; ks < 4; ++ks) {
            uint32_t afr[2][4], bfr[2][4];
            const int u = ks * 2 + uA_half;
            #pragma unroll
            for (int mt = 0; mt < 2; ++mt) {
                const int m = mrowA + mt * 16;
                ldsm4(Ab + m * 128 + ((u ^ (m & 7)) << 4), afr[mt]);
            }
            const int ub = ks * 2 + uB_half;
            #pragma unroll
            for (int np = 0; np < 2; ++np) {
                const int n = nrowB + np * 16;
                ldsm4(Bb + n * 128 + ((ub ^ (n & 7)) << 4), bfr[np]);
            }
            #pragma unroll
            for (int mt = 0; mt < 2; ++mt)
                #pragma unroll
                for (int np = 0; np < 2; ++np) {
                    mma16816(acc[mt][np * 2 + 0], afr[mt], bfr[np][0], bfr[np][1]);
                    mma16816(acc[mt][np * 2 + 1], afr[mt], bfr[np][2], bfr[np][3]);
                }
        }
    }

    // ---- Epilogue: exp + row sums (and col sums for off-diagonal tiles) ----
    const int gq = lane >> 2, tq = lane & 3;
    float accRow[2][2], accCol[4][2];
    #pragma unroll
    for (int a = 0; a < 2; ++a) { accRow[a][0] = accRow[a][1] = 0.f; }
    #pragma unroll
    for (int a = 0; a < 4; ++a) { accCol[a][0] = accCol[a][1] = 0.f; }

    #pragma unroll
    for (int mt = 0; mt < 2; ++mt)
        #pragma unroll
        for (int nn = 0; nn < 4; ++nn)
            #pragma unroll
            for (int i = 0; i < 4; ++i) {
                float e = exp10x(acc[mt][nn][i]);
                if (diag) {
                    const int dR = warp_m * 32 + mt * 16 + gq + (i >> 1) * 8;
                    const int dC = warp_n * 32 + nn * 8 + tq * 2 + (i & 1);
                    if (dR == dC) e = 0.f;
                }
                accRow[mt][i >> 1] += e;
                accCol[nn][i & 1]  += e;
            }

    #pragma unroll
    for (int o = 1; o <= 2; o <<= 1)
        #pragma unroll
        for (int mt = 0; mt < 2; ++mt) {
            accRow[mt][0] += __shfl_xor_sync(0xffffffffu, accRow[mt][0], o);
            accRow[mt][1] += __shfl_xor_sync(0xffffffffu, accRow[mt][1], o);
        }
    if (!diag) {
        #pragma unroll
        for (int o = 4; o <= 16; o <<= 1)
            #pragma unroll
            for (int nn = 0; nn < 4; ++nn) {
                accCol[nn][0] += __shfl_xor_sync(0xffffffffu, accCol[nn][0], o);
                accCol[nn][1] += __shfl_xor_sync(0xffffffffu, accCol[nn][1], o);
            }
    }

    // sRow/sCol were zeroed at kernel entry; the mainloop barriers ordered it.
    if (tq == 0) {
        #pragma unroll
        for (int mt = 0; mt < 2; ++mt)
            #pragma unroll
            for (int ih = 0; ih < 2; ++ih)
                atomicAdd(&sRow[warp_m * 32 + mt * 16 + gq + ih * 8], accRow[mt][ih]);
    }
    if (!diag && gq == 0) {
        #pragma unroll
        for (int nn = 0; nn < 4; ++nn)
            #pragma unroll
            for (int j = 0; j < 2; ++j)
                atomicAdd(&sCol[warp_n * 32 + nn * 8 + tq * 2 + j], accCol[nn][j]);
    }
    __syncthreads();
    if (tid < BT) {
        atomicAdd(&g_rowExp[rowBase + tid], sRow[tid]);
        if (!diag) atomicAdd(&g_rowExp[colBase + tid], sCol[tid]);
    }
}

// ---------------------------------------------------------------------------
// Kernel 3: per-row loss + global mean (separate launch; cheap)
// ---------------------------------------------------------------------------
__global__ void finalize_kernel(float* __restrict__ out) {
    int tid = threadIdx.x;   // 1024 threads
    float s = 0.f;
    #pragma unroll
    for (int k = 0; k < 4; ++k) {
        int r = tid + k * 1024;
        s += g_rowNum[r] * NEG_INV - __logf(g_rowExp[r]);
    }
    #pragma unroll
    for (int o = 16; o; o >>= 1) s += __shfl_xor_sync(0xffffffffu, s, o);
    __shared__ float ws[32];
    if ((tid & 31) == 0) ws[tid >> 5] = s;
    __syncthreads();
    if (tid < 32) {
        float v = ws[tid];
        #pragma unroll
        for (int o = 16; o; o >>= 1) v += __shfl_xor_sync(0xffffffffu, v, o);
        if (tid == 0) out[0] = -v / (float)M_TOT;
    }
}

// ---------------------------------------------------------------------------
extern "C" void kernel_launch(void* const* d_in, const int* in_sizes, int n_in,
                              void* d_out, int out_size) {
    const float* z = (const float*)d_in[0];
    if (n_in > 1 && in_sizes[0] != M_TOT * DIM) z = (const float*)d_in[1];

    cudaFuncSetAttribute(prep_kernel, cudaFuncAttributeMaxDynamicSharedMemorySize, PREP_SMEM);
    cudaFuncSetAttribute(gemm_kernel, cudaFuncAttributeMaxDynamicSharedMemorySize, SMEM_BYTES);

    prep_kernel<<<128, 1024, PREP_SMEM>>>(z);
    gemm_kernel<<<528, 512, SMEM_BYTES>>>();
    finalize_kernel<<<1, 1024>>>((float*)d_out);
}